// round 4
// baseline (speedup 1.0000x reference)
#include <cuda_runtime.h>
#include <cstdint>

// ProdEinsumTC: out[a,b,c,d,g] = (1/3) * sum_{e,f} T1[a,b,c,d,e,f] * T2[b,c,e,f,g]
// T1: (4, 131072, 6, 27) fp32   T2: (131072, 6, 27) fp32   out: (4, 131072, 6, 9)
//
// R4: persistent grid-stride blocks + per-warp software pipeline.
//  - 912 blocks (152 SM x 6 resident) loop over the 12288 block-tiles: no CTA churn.
//  - Each warp: wait -> compute -> syncwarp -> prefetch next tile's cp.async into
//    the same smem region -> store current outputs (overlapping in-flight loads).
//    A load group is outstanding at all times except the ~150-cycle compute window.
//  - Direct STG.32 stores (9/thread, 288B contiguous per path/warp: sectors fully
//    covered, merged in LTS).

#define BC        786432
#define BC27      ((size_t)BC * 27)
#define BC9       ((size_t)BC * 9)
#define WBC       8                 // bc pairs per warp-tile
#define WARPS     8                 // warps per block
#define NTHREADS  (WARPS * 32)
#define WARP_F    (WBC * 27 * 5)    // 1080 floats per warp region (4xT1 + T2)
#define NBT       (BC / (WARPS * WBC))   // 12288 block-tiles
#define GRID      912               // 152 SMs x 6 resident blocks
#define NORM      (0.3333333333333333f)

__device__ __forceinline__ void cp_async16(uint32_t dst, const void* src) {
    asm volatile("cp.async.cg.shared.global [%0], [%1], 16;\n"
                 :: "r"(dst), "l"(src));
}
__device__ __forceinline__ uint32_t smem_u32(const void* p) {
    uint32_t a;
    asm("{ .reg .u64 t; cvta.to.shared.u64 t, %1; cvt.u32.u64 %0, t; }"
        : "=r"(a) : "l"(p));
    return a;
}

// Issue the full 270-float4 warp-tile load (4 T1 segments + T2), coalesced,
// 16B-aligned, one commit group.
__device__ __forceinline__ void issue_tile(const float* __restrict__ T1,
                                           const float* __restrict__ T2,
                                           size_t bc0, uint32_t sw_u32, int lane)
{
    #pragma unroll
    for (int a = 0; a < 4; ++a) {
        const float4* __restrict__ g1 =
            (const float4*)(T1 + (size_t)a * BC27 + bc0 * 27);
        cp_async16(sw_u32 + (a * 54 + lane) * 16, g1 + lane);
        if (lane < 22)
            cp_async16(sw_u32 + (a * 54 + 32 + lane) * 16, g1 + 32 + lane);
    }
    const float4* __restrict__ g2 = (const float4*)(T2 + bc0 * 27);
    cp_async16(sw_u32 + (216 + lane) * 16, g2 + lane);
    if (lane < 22)
        cp_async16(sw_u32 + (216 + 32 + lane) * 16, g2 + 32 + lane);
    asm volatile("cp.async.commit_group;\n");
}

__global__ __launch_bounds__(NTHREADS, 6)
void prod_einsum_kernel(const float* __restrict__ T1,
                        const float* __restrict__ T2,
                        float* __restrict__ out)
{
    __shared__ __align__(16) float smem[WARPS * WARP_F];   // 34560 B

    const int tid  = threadIdx.x;
    const int w    = tid >> 5;
    const int lane = tid & 31;
    const int a    = lane >> 3;     // 0..3
    const int bcl  = lane & 7;      // 0..7

    float* const swarp = smem + w * WARP_F;
    const uint32_t sw_u32 = smem_u32(swarp);

    const float* __restrict__ t1p = swarp + a * 216 + bcl * 27;  // [d][e][f]
    const float* __restrict__ t2p = swarp + 864 + bcl * 27;      // [e][f][g]

    int bt = blockIdx.x;
    // Prologue: issue loads for first tile.
    issue_tile(T1, T2, ((size_t)bt * WARPS + w) * WBC, sw_u32, lane);

    while (true) {
        const size_t bc0 = ((size_t)bt * WARPS + w) * WBC;
        const int next_bt = bt + GRID;

        asm volatile("cp.async.wait_group 0;\n" ::: "memory");
        __syncwarp();

        // ---- Compute: 54 conflict-free LDS.32, 81 FMA ----
        float acc[9];
        #pragma unroll
        for (int i = 0; i < 9; ++i) acc[i] = 0.0f;

        #pragma unroll
        for (int k = 0; k < 9; ++k) {                 // k = e*3 + f
            const float b0 = t2p[k * 3 + 0];
            const float b1 = t2p[k * 3 + 1];
            const float b2 = t2p[k * 3 + 2];
            #pragma unroll
            for (int d = 0; d < 3; ++d) {
                const float av = t1p[d * 9 + k];
                acc[d * 3 + 0] = fmaf(av, b0, acc[d * 3 + 0]);
                acc[d * 3 + 1] = fmaf(av, b1, acc[d * 3 + 1]);
                acc[d * 3 + 2] = fmaf(av, b2, acc[d * 3 + 2]);
            }
        }

        __syncwarp();   // all lanes done reading swarp -> safe to overwrite

        // ---- Prefetch next tile while we store (loads fly under the STGs) ----
        if (next_bt < NBT)
            issue_tile(T1, T2, ((size_t)next_bt * WARPS + w) * WBC, sw_u32, lane);

        // ---- Store: 9 contiguous floats/thread; per path each warp covers a
        //      contiguous 288B run -> sectors fully covered, merged in LTS. ----
        {
            float* __restrict__ o = out + (size_t)a * BC9 + (bc0 + bcl) * 9;
            #pragma unroll
            for (int j = 0; j < 9; ++j)
                o[j] = acc[j] * NORM;
        }

        if (next_bt >= NBT) break;
        bt = next_bt;
    }
}

extern "C" void kernel_launch(void* const* d_in, const int* in_sizes, int n_in,
                              void* d_out, int out_size)
{
    const float* T1 = (const float*)d_in[0];
    const float* T2 = (const float*)d_in[1];
    float* out = (float*)d_out;

    prod_einsum_kernel<<<GRID, NTHREADS>>>(T1, T2, out);
}